// round 9
// baseline (speedup 1.0000x reference)
#include <cuda_runtime.h>
#include <cuda_fp16.h>
#include <cstdint>

#define N_NODES 8192
#define IN_F    128
#define OUT_F   64
#define ALPHA   0.2f
#define MAX_NBR 512      // nbrs/row = 164 +- 13; 512 is ~27 sigma

// Scratch (allocation-free rule: __device__ globals)
__device__ __align__(16) __half2 g_Wh2[N_NODES * (OUT_F / 2)];   // 1 MB, fp16 Wh
__device__ float g_s1[N_NODES];
__device__ float g_s2[N_NODES];

// ---------------------------------------------------------------------------
// Kernel 1: Wh = H @ W  (+ s_src, s_dst folded in), fp32 math, fp16 store.
// 128 blocks x 256 threads; tile 64 rows x 64 cols; thread = 4 rows x 4 cols.
// ---------------------------------------------------------------------------
__global__ __launch_bounds__(256) void wh_kernel(const float* __restrict__ H,
                                                 const float* __restrict__ W,
                                                 const float* __restrict__ a) {
    extern __shared__ __align__(16) float dynw[];
    float* sW  = dynw;                 // 128*64 = 32 KB
    float* sIn = dynw + IN_F * OUT_F;  // 64*128 = 32 KB
    int tid  = threadIdx.x;
    int row0 = blockIdx.x * 64;

    const float4* Wv = (const float4*)W;
    float4* sWv = (float4*)sW;
#pragma unroll
    for (int i = 0; i < 8; i++) sWv[tid + 256 * i] = Wv[tid + 256 * i];
    const float4* Hv = (const float4*)(H + (size_t)row0 * IN_F);
    float4* sInv = (float4*)sIn;
#pragma unroll
    for (int i = 0; i < 8; i++) sInv[tid + 256 * i] = Hv[tid + 256 * i];
    __syncthreads();

    int rl = tid >> 4;
    int cg = tid & 15;
    int c0 = cg * 4;
    int r0 = rl * 4;

    float4 acc[4] = {{0,0,0,0},{0,0,0,0},{0,0,0,0},{0,0,0,0}};

#pragma unroll 4
    for (int k0 = 0; k0 < IN_F; k0 += 4) {
        float4 a4[4];
#pragma unroll
        for (int r = 0; r < 4; r++)
            a4[r] = *(const float4*)&sIn[(r0 + r) * IN_F + k0];
#pragma unroll
        for (int kk = 0; kk < 4; kk++) {
            float4 w = *(const float4*)&sW[(k0 + kk) * OUT_F + c0];
#pragma unroll
            for (int r = 0; r < 4; r++) {
                float hv = ((const float*)&a4[r])[kk];
                acc[r].x += hv * w.x; acc[r].y += hv * w.y;
                acc[r].z += hv * w.z; acc[r].w += hv * w.w;
            }
        }
    }

    float4 a1q = *(const float4*)&a[c0];
    float4 a2q = *(const float4*)&a[OUT_F + c0];
#pragma unroll
    for (int r = 0; r < 4; r++) {
        int row = row0 + r0 + r;
        g_Wh2[row * (OUT_F / 2) + cg * 2]     = __floats2half2_rn(acc[r].x, acc[r].y);
        g_Wh2[row * (OUT_F / 2) + cg * 2 + 1] = __floats2half2_rn(acc[r].z, acc[r].w);
        float s1 = acc[r].x * a1q.x + acc[r].y * a1q.y + acc[r].z * a1q.z + acc[r].w * a1q.w;
        float s2 = acc[r].x * a2q.x + acc[r].y * a2q.y + acc[r].z * a2q.z + acc[r].w * a2q.w;
#pragma unroll
        for (int d = 8; d >= 1; d >>= 1) {
            s1 += __shfl_down_sync(0xffffffffu, s1, d, 16);
            s2 += __shfl_down_sync(0xffffffffu, s2, d, 16);
        }
        if (cg == 0) { g_s1[row] = s1; g_s2[row] = s2; }
    }
}

// ---------------------------------------------------------------------------
// Kernel 2: one adjacency row per 256-thread block (8192 blocks).
// m32 fused bitmask compaction; fp16 Wh gathers as 8-lane LDG.128 per edge
// (32 neighbor groups -> ~5 gather iterations); two-stage partial reduce.
// Softmax without max-shift (|s| << 87, fp32-safe; ratios exact).
// ---------------------------------------------------------------------------
__global__ __launch_bounds__(256) void gat_row_kernel(const float* __restrict__ adj,
                                                      float* __restrict__ out) {
    __shared__ __align__(16) float2 s_ew[MAX_NBR];        // {Wh byte offset, weight}
    __shared__ __align__(16) float  s_part[32 * OUT_F];   // 8 KB partials
    __shared__ __align__(16) float  s_p2[256];            // stage-2 partials
    __shared__ int   s_woff[9];
    __shared__ float s_red[8];
    __shared__ float s_bcast;

    int tid  = threadIdx.x;
    int lane = tid & 31;
    int wid  = tid >> 5;
    int row  = blockIdx.x;

    // --- Stream adj row; one fused 32-bit edge mask per thread ---
    const float4* arow = (const float4*)(adj + (size_t)row * N_NODES);
    unsigned m32 = 0;
#pragma unroll
    for (int it = 0; it < 8; it++) {
        float4 v = __ldcs(&arow[it * 256 + tid]);
        unsigned m = (v.x != 0.f ? 1u : 0u) | (v.y != 0.f ? 2u : 0u)
                   | (v.z != 0.f ? 4u : 0u) | (v.w != 0.f ? 8u : 0u);
        m32 |= m << (it * 4);
    }
    int cnt = __popc(m32);

    // --- Deterministic block exclusive scan of per-thread counts ---
    int inc = cnt;
#pragma unroll
    for (int d = 1; d < 32; d <<= 1) {
        int t = __shfl_up_sync(0xffffffffu, inc, d);
        if (lane >= d) inc += t;
    }
    if (lane == 31) s_woff[wid] = inc;
    __syncthreads();
    if (tid == 0) {
        int run = 0;
#pragma unroll
        for (int w2 = 0; w2 < 8; w2++) { int t = s_woff[w2]; s_woff[w2] = run; run += t; }
        s_woff[8] = run;
    }
    __syncthreads();

    int off = s_woff[wid] + (inc - cnt);
    int n = s_woff[8];
    if (n > MAX_NBR) n = MAX_NBR;

    // --- Single compaction loop fused with p = exp(leaky_relu(si+sj)) ---
    float si = g_s1[row];
    float lsum = 0.f;
    int tcol = tid << 2;
    unsigned m = m32;
    while (m) {
        int bit = __ffs(m) - 1;
        m &= m - 1;
        int j = ((bit >> 2) << 10) + tcol + (bit & 3);
        if (off < MAX_NBR) {
            float s = si + g_s2[j];
            s = fmaxf(s, ALPHA * s);
            float p = __expf(s);
            s_ew[off] = make_float2(__int_as_float(j * 128), p);  // 128 B fp16 row
            lsum += p;
        }
        off++;
    }

    // --- Softmax denominator (single block reduction) ---
#pragma unroll
    for (int d = 16; d >= 1; d >>= 1)
        lsum += __shfl_down_sync(0xffffffffu, lsum, d);
    if (lane == 0) s_red[wid] = lsum;
    __syncthreads();
    if (tid == 0) {
        float s = 0.f;
#pragma unroll
        for (int w2 = 0; w2 < 8; w2++) s += s_red[w2];
        s_bcast = 1.f / s;
    }
    __syncthreads();
    float inv = s_bcast;

    // --- Gather: 8 lanes x LDG.128 per edge; 32 nbr groups, ~5 iters ---
    int e = tid & 7;            // feature octet 0..7 (8 features = 16 B)
    int g = tid >> 3;           // neighbor group 0..31
    const char* wbase = (const char*)g_Wh2 + e * 16;
    float a0 = 0.f, a1 = 0.f, a2 = 0.f, a3 = 0.f;
    float a4 = 0.f, a5 = 0.f, a6 = 0.f, a7 = 0.f;
    for (int k = g; k < n; k += 32) {
        float2 ew = s_ew[k];
        uint4 u = *(const uint4*)(wbase + __float_as_int(ew.x));
        float w = ew.y;
        float2 f0 = __half22float2(*(__half2*)&u.x);
        float2 f1 = __half22float2(*(__half2*)&u.y);
        float2 f2 = __half22float2(*(__half2*)&u.z);
        float2 f3 = __half22float2(*(__half2*)&u.w);
        a0 += w * f0.x; a1 += w * f0.y; a2 += w * f1.x; a3 += w * f1.y;
        a4 += w * f2.x; a5 += w * f2.y; a6 += w * f3.x; a7 += w * f3.y;
    }
    *(float4*)&s_part[g * OUT_F + e * 8]     = make_float4(a0, a1, a2, a3);
    *(float4*)&s_part[g * OUT_F + e * 8 + 4] = make_float4(a4, a5, a6, a7);
    __syncthreads();

    // --- Two-stage reduce over 32 groups ---
    {
        int f = tid & 63;       // feature
        int c = tid >> 6;       // chunk 0..3 (groups c*8..c*8+7); warp-uniform
        float r = 0.f;
#pragma unroll
        for (int i = 0; i < 8; i++) r += s_part[(c * 8 + i) * OUT_F + f];
        s_p2[c * 64 + f] = r;
    }
    __syncthreads();
    if (tid < OUT_F) {
        float r = s_p2[tid] + s_p2[64 + tid] + s_p2[128 + tid] + s_p2[192 + tid];
        out[(size_t)row * OUT_F + tid] = r * inv;
    }
}

// ---------------------------------------------------------------------------
extern "C" void kernel_launch(void* const* d_in, const int* in_sizes, int n_in,
                              void* d_out, int out_size) {
    const float* H   = (const float*)d_in[0];  // [8192,128]
    const float* adj = (const float*)d_in[1];  // [8192,8192]
    const float* W   = (const float*)d_in[2];  // [128,64]
    const float* a   = (const float*)d_in[3];  // [128,1]
    float* out = (float*)d_out;                // [8192,64]

    const int wh_smem = (IN_F * OUT_F + 64 * IN_F) * 4;   // 64 KB
    cudaFuncSetAttribute(wh_kernel,
                         cudaFuncAttributeMaxDynamicSharedMemorySize, wh_smem);

    wh_kernel<<<N_NODES / 64, 256, wh_smem>>>(H, W, a);
    gat_row_kernel<<<N_NODES, 256>>>(adj, out);
}